// round 2
// baseline (speedup 1.0000x reference)
#include <cuda_runtime.h>
#include <math.h>

#define BN_INV 0.9999950000374997f

// ---------------- scratch (device globals; no allocations allowed) -----------
__device__ float g_p1[8 * 32 * 128 * 128];   // maxpool(e1)
__device__ float g_p2[8 * 64 * 64 * 64];     // maxpool(e2)
__device__ float g_p3[8 * 128 * 32 * 32];    // maxpool(e3)
__device__ float g_e4[8 * 256 * 32 * 32];    // conv4 output
__device__ float g_A [256 * 16 * 16];        // per-channel quadratic forms

// ---------------- conv1: Cin=1 -> Cout=32, H=W=256, pad 1, BN+ReLU ----------
// grid (4,16,8), block 256 = 16x16. Each thread: 4 consecutive x pixels, all 32 oc.
__global__ __launch_bounds__(256) void conv1_kernel(
    const float* __restrict__ x, const float* __restrict__ w,
    const float* __restrict__ g, const float* __restrict__ b,
    float* __restrict__ out)
{
    __shared__ float ws[32 * 9];
    __shared__ float ss[32], bs[32];
    __shared__ float tile[18][66];

    const int tid = threadIdx.x;
    for (int i = tid; i < 288; i += 256) ws[i] = w[i];
    if (tid < 32) {
        ss[tid] = g[tid] * BN_INV;
        bs[tid] = b[tid];
    }
    const int n  = blockIdx.z;
    const int y0 = blockIdx.y * 16;
    const int x0 = blockIdx.x * 64;
    const float* xp = x + (long)n * 65536;

    for (int i = tid; i < 18 * 66; i += 256) {
        int r = i / 66, c = i % 66;
        int yy = y0 - 1 + r, xx = x0 - 1 + c;
        float v = 0.f;
        if (yy >= 0 && yy < 256 && xx >= 0 && xx < 256) v = xp[yy * 256 + xx];
        tile[r][c] = v;
    }
    __syncthreads();

    const int tx = tid & 15, ty = tid >> 4;
    float win[3][6];
#pragma unroll
    for (int r = 0; r < 3; r++)
#pragma unroll
        for (int c = 0; c < 6; c++) win[r][c] = tile[ty + r][tx * 4 + c];

    const int y = y0 + ty, xb = x0 + tx * 4;
    float* op = out + (long)n * 32 * 65536 + y * 256 + xb;

#pragma unroll
    for (int cb = 0; cb < 4; cb++) {
        float acc[8][4];
#pragma unroll
        for (int c = 0; c < 8; c++)
#pragma unroll
            for (int p = 0; p < 4; p++) acc[c][p] = 0.f;
#pragma unroll
        for (int c = 0; c < 8; c++) {
            int ch = cb * 8 + c;
#pragma unroll
            for (int ky = 0; ky < 3; ky++)
#pragma unroll
                for (int kx = 0; kx < 3; kx++) {
                    float wv = ws[ch * 9 + ky * 3 + kx];
#pragma unroll
                    for (int p = 0; p < 4; p++) acc[c][p] += wv * win[ky][kx + p];
                }
        }
#pragma unroll
        for (int c = 0; c < 8; c++) {
            int ch = cb * 8 + c;
            float s = ss[ch], bb = bs[ch];
            float4 v;
            v.x = fmaxf(acc[c][0] * s + bb, 0.f);
            v.y = fmaxf(acc[c][1] * s + bb, 0.f);
            v.z = fmaxf(acc[c][2] * s + bb, 0.f);
            v.w = fmaxf(acc[c][3] * s + bb, 0.f);
            *(float4*)(op + (long)ch * 65536) = v;
        }
    }
}

// ---------------- generic conv: Cin multiple of 16, BN+ReLU -----------------
// grid (W/32, H/8, N*Cout/32), block 256 = (tx:8, ty:8, tg:4)
// thread: 4 x-pixels x 8 oc register tile; cin chunked by 16 through smem.
#define CC 16
__global__ __launch_bounds__(256) void conv_kernel(
    const float* __restrict__ in, const float* __restrict__ w,
    const float* __restrict__ g, const float* __restrict__ b,
    float* __restrict__ out, int Cin, int H, int W, int Cout)
{
    __shared__ float in_s[CC][10][35];   // stride 35: conflict-free for 4*tx+3*ty
    __shared__ float w_s[CC * 9 * 32];   // [ic][kk][oc]
    __shared__ float ss[32], bs[32];

    const int tid = threadIdx.x;
    const int nOcb = Cout >> 5;
    const int n    = blockIdx.z / nOcb;
    const int ocb  = (blockIdx.z % nOcb) * 32;
    const int y0   = blockIdx.y * 8;
    const int x0   = blockIdx.x * 32;
    if (tid < 32) { ss[tid] = g[ocb + tid] * BN_INV; bs[tid] = b[ocb + tid]; }

    const int tx = tid & 7, ty = (tid >> 3) & 7, tg = tid >> 6;
    const long HW = (long)H * W;

    float acc[8][4];
#pragma unroll
    for (int o = 0; o < 8; o++)
#pragma unroll
        for (int p = 0; p < 4; p++) acc[o][p] = 0.f;

    for (int ic0 = 0; ic0 < Cin; ic0 += CC) {
        __syncthreads();
        // input tile: rows y0-1..y0+8, cols x0-1..x0+32 (10 x 34) x 16 ic
        for (int i = tid; i < CC * 10 * 34; i += 256) {
            int ic = i / 340, rem = i % 340;
            int r = rem / 34, c = rem % 34;
            int yy = y0 - 1 + r, xx = x0 - 1 + c;
            float v = 0.f;
            if (yy >= 0 && yy < H && xx >= 0 && xx < W)
                v = in[((long)n * Cin + ic0 + ic) * HW + (long)yy * W + xx];
            in_s[ic][r][c] = v;
        }
        // weights OIHW -> [ic][kk][oc]
        for (int i = tid; i < CC * 9 * 32; i += 256) {
            int oc = i & 31;
            int rem = i >> 5;            // ic*9 + kk
            int kk = rem % 9, ic = rem / 9;
            w_s[i] = w[((long)(ocb + oc) * Cin + ic0 + ic) * 9 + kk];
        }
        __syncthreads();

        for (int ic = 0; ic < CC; ic++) {
#pragma unroll
            for (int ky = 0; ky < 3; ky++) {
                float rr[6];
#pragma unroll
                for (int c = 0; c < 6; c++) rr[c] = in_s[ic][ty + ky][tx * 4 + c];
#pragma unroll
                for (int kx = 0; kx < 3; kx++) {
                    const float4* wp = (const float4*)&w_s[(ic * 9 + ky * 3 + kx) * 32 + tg * 8];
                    float4 wa = wp[0], wb = wp[1];
                    float w8[8] = {wa.x, wa.y, wa.z, wa.w, wb.x, wb.y, wb.z, wb.w};
#pragma unroll
                    for (int o = 0; o < 8; o++)
#pragma unroll
                        for (int p = 0; p < 4; p++)
                            acc[o][p] += w8[o] * rr[kx + p];
                }
            }
        }
    }

    const int y = y0 + ty;
    float* op = out + ((long)n * Cout + ocb + tg * 8) * HW + (long)y * W + x0 + tx * 4;
#pragma unroll
    for (int o = 0; o < 8; o++) {
        float s = ss[tg * 8 + o], bb = bs[tg * 8 + o];
        float4 v;
        v.x = fmaxf(acc[o][0] * s + bb, 0.f);
        v.y = fmaxf(acc[o][1] * s + bb, 0.f);
        v.z = fmaxf(acc[o][2] * s + bb, 0.f);
        v.w = fmaxf(acc[o][3] * s + bb, 0.f);
        *(float4*)(op + (long)o * HW) = v;
    }
}

// ---------------- 2x2 maxpool, float4 vectorized -----------------------------
__global__ void pool_kernel(const float* __restrict__ in, float* __restrict__ out,
                            int Wi, int Wo, int Ho, long total4)
{
    long t = (long)blockIdx.x * blockDim.x + threadIdx.x;
    if (t >= total4) return;
    int wq = Wo >> 2;
    int xq = (int)(t % wq);
    long r = t / wq;
    int yo = (int)(r % Ho);
    long pl = r / Ho;
    const float* p0 = in + pl * (long)Wi * 2 * Ho + (long)(2 * yo) * Wi + xq * 8;
    const float* p1 = p0 + Wi;
    float4 a0 = ((const float4*)p0)[0], a1 = ((const float4*)p0)[1];
    float4 b0 = ((const float4*)p1)[0], b1 = ((const float4*)p1)[1];
    float4 o;
    o.x = fmaxf(fmaxf(a0.x, a0.y), fmaxf(b0.x, b0.y));
    o.y = fmaxf(fmaxf(a0.z, a0.w), fmaxf(b0.z, b0.w));
    o.z = fmaxf(fmaxf(a1.x, a1.y), fmaxf(b1.x, b1.y));
    o.w = fmaxf(fmaxf(a1.z, a1.w), fmaxf(b1.z, b1.w));
    *(float4*)(out + pl * (long)Ho * Wo + (long)yo * Wo + xq * 4) = o;
}

// ---------------- build per-channel quadratic form A = Re(U^H diag(zbar) U) --
// one thread per (channel c, column k): computes A[c][j][k] for all j.
__global__ void build_A_kernel(const float* __restrict__ w0,
                               const float* __restrict__ w1,
                               float* __restrict__ A)
{
    int t = blockIdx.x * blockDim.x + threadIdx.x;
    if (t >= 256 * 16) return;
    int c = t >> 4, k = t & 15;

    float gr[4][2][2], gi[4][2][2];
    float a0 = w0[c * 2 + 0], a1 = w0[c * 2 + 1];
    float z0 = w1[c * 2 + 0], z1 = w1[c * 2 + 1];
    const float isq2 = 0.7071067811865476f;
#pragma unroll
    for (int w = 0; w < 4; w++) {
        float ay = (w & 1) ? a1 : a0;
        float az = (w & 1) ? z1 : z0;
        float cy = cosf(ay * 0.5f), sy = sinf(ay * 0.5f);
        float cz = cosf(az * 0.5f), sz = sinf(az * 0.5f);
        float m00 = (cy - sy) * isq2, m01 = (cy + sy) * isq2;
        float m10 = (sy + cy) * isq2, m11 = (sy - cy) * isq2;
        gr[w][0][0] = m00 * cz; gi[w][0][0] = -m00 * sz;
        gr[w][0][1] = m01 * cz; gi[w][0][1] = -m01 * sz;
        gr[w][1][0] = m10 * cz; gi[w][1][0] =  m10 * sz;
        gr[w][1][1] = m11 * cz; gi[w][1][1] =  m11 * sz;
    }
    // PTOT = p01 o p12 o p23 o p30 (applied to b in that order)
    int P[16];
#pragma unroll
    for (int bb = 0; bb < 16; bb++) {
        int v = bb;
        if (v & 1) v ^= 8;   // CNOT(3,0)
        if (v & 2) v ^= 1;   // CNOT(2,3)
        if (v & 4) v ^= 2;   // CNOT(1,2)
        if (v & 8) v ^= 4;   // CNOT(0,1)
        P[bb] = v;
    }

    float acc[16];
#pragma unroll
    for (int j = 0; j < 16; j++) acc[j] = 0.f;

    for (int i = 0; i < 16; i++) {
        int r = P[i];
        float zi = (4 - 2 * __popc(i)) * 0.25f;
        int r0 = (r >> 3) & 1, r1 = (r >> 2) & 1, r2 = (r >> 1) & 1, r3 = r & 1;

        float t2r[2], t2i[2];
        t2r[0] = gr[0][r0][0]; t2i[0] = gi[0][r0][0];
        t2r[1] = gr[0][r0][1]; t2i[1] = gi[0][r0][1];
        float t4r[4], t4i[4];
#pragma unroll
        for (int j0 = 0; j0 < 2; j0++)
#pragma unroll
            for (int j1 = 0; j1 < 2; j1++) {
                float br = gr[1][r1][j1], bi = gi[1][r1][j1];
                t4r[j0 * 2 + j1] = t2r[j0] * br - t2i[j0] * bi;
                t4i[j0 * 2 + j1] = t2r[j0] * bi + t2i[j0] * br;
            }
        float t8r[8], t8i[8];
#pragma unroll
        for (int j = 0; j < 4; j++)
#pragma unroll
            for (int j2 = 0; j2 < 2; j2++) {
                float br = gr[2][r2][j2], bi = gi[2][r2][j2];
                t8r[j * 2 + j2] = t4r[j] * br - t4i[j] * bi;
                t8i[j * 2 + j2] = t4r[j] * bi + t4i[j] * br;
            }
        float ur[16], ui[16];
#pragma unroll
        for (int j = 0; j < 8; j++)
#pragma unroll
            for (int j3 = 0; j3 < 2; j3++) {
                float br = gr[3][r3][j3], bi = gi[3][r3][j3];
                ur[j * 2 + j3] = t8r[j] * br - t8i[j] * bi;
                ui[j * 2 + j3] = t8r[j] * bi + t8i[j] * br;
            }
        float ukr = ur[k], uki = ui[k];
#pragma unroll
        for (int j = 0; j < 16; j++)
            acc[j] += zi * (ur[j] * ukr + ui[j] * uki);
    }
#pragma unroll
    for (int j = 0; j < 16; j++) A[c * 256 + j * 16 + k] = acc[j];
}

// ---------------- quantum stage + BN5 + ReLU (fused) -------------------------
// one block per (n,c) plane (32x32). thread: 4 consecutive x outputs.
__global__ __launch_bounds__(256) void quantum_kernel(
    const float* __restrict__ e4, const float* __restrict__ A,
    const float* __restrict__ g5, const float* __restrict__ b5,
    float* __restrict__ out)
{
    __shared__ float tile[35 * 37];  // stride 37: conflict-free
    __shared__ float As[256];

    const int bc = blockIdx.x;       // n*256 + c
    const int c  = bc & 255;
    const int tid = threadIdx.x;

    for (int i = tid; i < 35 * 37; i += 256) tile[i] = 0.f;
    __syncthreads();
    const float* ep = e4 + (long)bc * 1024;
    for (int i = tid; i < 1024; i += 256) {
        int r = i >> 5, cc = i & 31;
        tile[(r + 1) * 37 + (cc + 1)] = ep[i];
    }
    if (tid < 256) As[tid] = A[c * 256 + tid];
    __syncthreads();

    const int y = tid >> 3, x4 = (tid & 7) * 4;
    float win[4][7];
#pragma unroll
    for (int r = 0; r < 4; r++)
#pragma unroll
        for (int cc = 0; cc < 7; cc++) win[r][cc] = tile[(y + r) * 37 + x4 + cc];

    float s[4] = {0.f, 0.f, 0.f, 0.f};
#pragma unroll
    for (int o = 0; o < 4; o++)
#pragma unroll
        for (int t = 0; t < 16; t++) {
            float v = win[t >> 2][(t & 3) + o];
            s[o] += v * v;
        }

    float quad[4] = {0.f, 0.f, 0.f, 0.f};
#pragma unroll
    for (int j = 0; j < 16; j++) {
        float t0 = 0.f, t1 = 0.f, t2 = 0.f, t3 = 0.f;
        int jr = j >> 2, jc = j & 3;
#pragma unroll
        for (int k = 0; k < 16; k++) {
            float a = As[j * 16 + k];
            int kr = k >> 2, kc = k & 3;
            t0 += a * win[kr][kc + 0];
            t1 += a * win[kr][kc + 1];
            t2 += a * win[kr][kc + 2];
            t3 += a * win[kr][kc + 3];
        }
        quad[0] += t0 * win[jr][jc + 0];
        quad[1] += t1 * win[jr][jc + 1];
        quad[2] += t2 * win[jr][jc + 2];
        quad[3] += t3 * win[jr][jc + 3];
    }

    const float sc = g5[c] * BN_INV, bb = b5[c];
    float4 v;
    v.x = fmaxf((0.5f * quad[0] / fmaxf(s[0], 1e-24f) + 0.5f) * sc + bb, 0.f);
    v.y = fmaxf((0.5f * quad[1] / fmaxf(s[1], 1e-24f) + 0.5f) * sc + bb, 0.f);
    v.z = fmaxf((0.5f * quad[2] / fmaxf(s[2], 1e-24f) + 0.5f) * sc + bb, 0.f);
    v.w = fmaxf((0.5f * quad[3] / fmaxf(s[3], 1e-24f) + 0.5f) * sc + bb, 0.f);
    *(float4*)(out + (long)bc * 1024 + y * 32 + x4) = v;
}

// -----------------------------------------------------------------------------
extern "C" void kernel_launch(void* const* d_in, const int* in_sizes, int n_in,
                              void* d_out, int out_size)
{
    (void)in_sizes; (void)n_in; (void)out_size;
    const float* x   = (const float*)d_in[0];
    const float* w1  = (const float*)d_in[1];
    const float* g1  = (const float*)d_in[2];
    const float* b1  = (const float*)d_in[3];
    const float* w2  = (const float*)d_in[4];
    const float* g2  = (const float*)d_in[5];
    const float* b2  = (const float*)d_in[6];
    const float* w3  = (const float*)d_in[7];
    const float* g3  = (const float*)d_in[8];
    const float* b3  = (const float*)d_in[9];
    const float* w4  = (const float*)d_in[10];
    const float* g4  = (const float*)d_in[11];
    const float* b4  = (const float*)d_in[12];
    const float* qw0 = (const float*)d_in[13];
    const float* qw1 = (const float*)d_in[14];
    const float* g5  = (const float*)d_in[15];
    const float* b5  = (const float*)d_in[16];

    float* out = (float*)d_out;
    float* e1 = out;
    float* e2 = out + 16777216;   // 8*32*256*256
    float* e3 = out + 25165824;   // + 8*64*128*128
    float* o4 = out + 29360128;   // + 8*128*64*64

    float *p1, *p2, *p3, *e4, *Ab;
    cudaGetSymbolAddress((void**)&p1, g_p1);
    cudaGetSymbolAddress((void**)&p2, g_p2);
    cudaGetSymbolAddress((void**)&p3, g_p3);
    cudaGetSymbolAddress((void**)&e4, g_e4);
    cudaGetSymbolAddress((void**)&Ab, g_A);

    // conv1: (8,1,256,256) -> e1 (8,32,256,256)
    conv1_kernel<<<dim3(4, 16, 8), 256>>>(x, w1, g1, b1, e1);
    // pool1 -> p1 (8,32,128,128)
    pool_kernel<<<4096, 256>>>(e1, p1, 256, 128, 128, 1048576L);
    // conv2 -> e2 (8,64,128,128)
    conv_kernel<<<dim3(4, 16, 8 * 2), 256>>>(p1, w2, g2, b2, e2, 32, 128, 128, 64);
    // pool2 -> p2 (8,64,64,64)
    pool_kernel<<<2048, 256>>>(e2, p2, 128, 64, 64, 524288L);
    // conv3 -> e3 (8,128,64,64)
    conv_kernel<<<dim3(2, 8, 8 * 4), 256>>>(p2, w3, g3, b3, e3, 64, 64, 64, 128);
    // pool3 -> p3 (8,128,32,32)
    pool_kernel<<<1024, 256>>>(e3, p3, 64, 32, 32, 262144L);
    // conv4 -> e4 (8,256,32,32)
    conv_kernel<<<dim3(1, 4, 8 * 8), 256>>>(p3, w4, g4, b4, e4, 128, 32, 32, 256);
    // quantum quadratic forms
    build_A_kernel<<<16, 256>>>(qw0, qw1, Ab);
    // quantum stage + BN5 + ReLU -> o4 (8,256,32,32)
    quantum_kernel<<<2048, 256>>>(e4, Ab, g5, b5, o4);
}